// round 11
// baseline (speedup 1.0000x reference)
#include <cuda_runtime.h>
#include <math.h>

// z[b] = sum_t x[b,t]*K[t] + z0 + e
// K[t] = sum_h w_h*b_h*a_h^(T-1-t),  z0 = sum_h w_h*c_h*(1-a_h^T)/(1-a_h)
#define TLEN 4096
#define HDIM 512
#define BATCH 64
#define CHUNK 16
#define NBLK 128          // single wave on 148 SMs (512 thr, 32KB smem each)
#define SPAN 32           // exponents per block = 2 tile rounds of 16

// Scratch (__device__ globals; zero-init; no allocations)
__device__ __align__(16) float g_K[TLEN];
__device__ unsigned g_bar;   // monotonic generation barrier (never reset)

__global__ __launch_bounds__(HDIM) void fused_kernel(
    const float* __restrict__ x, const float* __restrict__ a,
    const float* __restrict__ b, const float* __restrict__ c,
    const float* __restrict__ w, const float* __restrict__ e,
    float* __restrict__ out)
{
    __shared__ float part[CHUNK][HDIM];   // 32 KB
    __shared__ float zp[16];
    __shared__ float s_z0;
    __shared__ unsigned s_gen;

    const int tid = threadIdx.x;
    const int bid = blockIdx.x;
    const int warp = tid >> 5, lane = tid & 31;

    // ---- phase-2 x prefetch at entry: DRAM latency hides under phase 1 ----
    const int row = bid >> 1;
    const int seg = bid & 1;
    const float4 xv = ((const float4*)(x + (size_t)row * TLEN + seg * (TLEN / 2)))[tid];

    // ---- phase 1: K chunk [32b, 32b+32), single log2f/exp2f seed ----
    const float af  = a[tid];
    const float wb  = w[tid] * b[tid];
    const float l2a = log2f(af);          // relative-accurate (NOT __log2f)
    float p = wb * exp2f((float)(bid * SPAN) * l2a);

    // block 0: z0 partials (block-uniform branch; shfl is safe)
    if (bid == 0) {
        const float aT  = exp2f((float)TLEN * l2a);
        const float geo = (1.0f - aT) / (1.0f - af);
        float term = w[tid] * c[tid] * geo;
        #pragma unroll
        for (int off = 16; off; off >>= 1)
            term += __shfl_down_sync(0xffffffffu, term, off);
        if (lane == 0) zp[warp] = term;
    }

    #pragma unroll
    for (int r = 0; r < SPAN / CHUNK; r++) {
        #pragma unroll
        for (int i = 0; i < CHUNK; i++) { part[i][tid] = p; p *= af; }
        __syncthreads();
        // warp i reduces h-dimension for t-offset i of this round
        float s = 0.0f;
        #pragma unroll
        for (int k = 0; k < HDIM / 32; k++) s += part[warp][lane + 32 * k];
        #pragma unroll
        for (int off = 16; off; off >>= 1) s += __shfl_down_sync(0xffffffffu, s, off);
        if (lane == 0) g_K[TLEN - 1 - (bid * SPAN + r * CHUNK + warp)] = s;
        __syncthreads();
    }

    // block 0: finish z0, pre-init out[row] = z0 + e (published by the barrier)
    if (bid == 0) {
        if (tid == 0) {
            float sz = 0.0f;
            #pragma unroll
            for (int i = 0; i < 16; i++) sz += zp[i];
            s_z0 = sz + e[0];
        }
        __syncthreads();
        if (tid < BATCH) out[tid] = s_z0;
    }

    // ---- grid barrier (single wave; monotonic generation => replay-safe) ----
    __threadfence();                       // release this CTA's g_K/out stores
    __syncthreads();
    if (tid == 0) {
        unsigned my = atomicAdd(&g_bar, 1u);
        s_gen = (my >> 7);                 // 128 = 2^7 arrivals per generation
        const unsigned target = (s_gen + 1u) << 7;
        while (*((volatile unsigned*)&g_bar) < target) { __nanosleep(20); }
    }
    __syncthreads();
    __threadfence();                       // acquire

    // ---- phase 2: dot this block's 2 KB x-register slice with K from L2 ----
    const float4 kv = __ldcg(&((const float4*)g_K)[seg * (TLEN / 8) + tid]);

    float s = xv.x * kv.x + xv.y * kv.y + xv.z * kv.z + xv.w * kv.w;
    #pragma unroll
    for (int off = 16; off; off >>= 1) s += __shfl_down_sync(0xffffffffu, s, off);

    __shared__ float sp[16];
    if (lane == 0) sp[warp] = s;
    __syncthreads();
    if (warp == 0) {
        float t = (lane < 16) ? sp[lane] : 0.0f;
        #pragma unroll
        for (int off = 8; off; off >>= 1) t += __shfl_down_sync(0xffffffffu, t, off);
        if (lane == 0) atomicAdd(&out[row], t);   // 2 adds per row
    }
}

extern "C" void kernel_launch(void* const* d_in, const int* in_sizes, int n_in,
                              void* d_out, int out_size)
{
    const float* x = (const float*)d_in[0];   // [B, T]
    const float* a = (const float*)d_in[1];   // [H]
    const float* b = (const float*)d_in[2];   // [H]
    const float* c = (const float*)d_in[3];   // [H]
    const float* w = (const float*)d_in[4];   // [H]
    const float* e = (const float*)d_in[5];   // [1]
    float* out = (float*)d_out;               // [B]

    fused_kernel<<<NBLK, HDIM>>>(x, a, b, c, w, e, out);
}

// round 12
// speedup vs baseline: 3.2689x; 3.2689x over previous
#include <cuda_runtime.h>
#include <math.h>

// z[b] = sum_t x[b,t]*K[t] + z0 + e
// K[t] = sum_h w_h*b_h*a_h^(T-1-t),  z0 = sum_h w_h*c_h*(1-a_h^T)/(1-a_h)
#define TLEN 4096
#define HDIM 512
#define BATCH 64
#define CHUNK 16
#define NCHUNK (TLEN / CHUNK)   // 256 blocks

// Scratch (__device__ globals; no allocations allowed)
__device__ __align__(16) float g_K[TLEN];
__device__ float g_z0;

// Kernel 1: K chunk of 16 t's per block, seed via accurate log2f/exp2f.
__global__ __launch_bounds__(HDIM) void build_K_kernel(
    const float* __restrict__ a, const float* __restrict__ b,
    const float* __restrict__ c, const float* __restrict__ w)
{
    __shared__ float part[CHUNK][HDIM];   // 32 KB
    __shared__ float zp[16];
    const int h = threadIdx.x;
    const int j = blockIdx.x;             // exponents s in [16j, 16j+16)
    const int warp = h >> 5, lane = h & 31;

    // issue all LDGs up front so they overlap the MUFU chain
    const float af = a[h];
    const float bf = b[h];
    const float wf = w[h];

    const float l2a = log2f(af);          // relative-accurate (NOT __log2f)
    const float wb  = wf * bf;
    float p = wb * exp2f((float)(j * CHUNK) * l2a);

    #pragma unroll
    for (int i = 0; i < CHUNK; i++) { part[i][h] = p; p *= af; }

    if (j == 0) {                          // z0 = sum_h w*c*(1-a^T)/(1-a)
        const float aT  = exp2f((float)TLEN * l2a);
        const float geo = (1.0f - aT) / (1.0f - af);
        float term = wf * c[h] * geo;
        #pragma unroll
        for (int off = 16; off; off >>= 1)
            term += __shfl_down_sync(0xffffffffu, term, off);
        if (lane == 0) zp[warp] = term;
    }
    __syncthreads();

    // warp i reduces the h-dimension for t-offset i
    float s = 0.0f;
    #pragma unroll
    for (int k = 0; k < HDIM / 32; k++) s += part[warp][lane + 32 * k];
    #pragma unroll
    for (int off = 16; off; off >>= 1) s += __shfl_down_sync(0xffffffffu, s, off);
    if (lane == 0) g_K[TLEN - 1 - (j * CHUNK + warp)] = s;

    if (j == 0 && h == 0) {
        float sz = 0.0f;
        #pragma unroll
        for (int i = 0; i < 16; i++) sz += zp[i];
        g_z0 = sz;
    }

    // all K/z0 stores issued -> release the dependent grid
    asm volatile("griddepcontrol.launch_dependents;");
}

// Kernel 2 (PDL secondary): one block per batch row, 1024 threads,
// one float4 of x and K per thread.
__global__ __launch_bounds__(1024) void dot_kernel(
    const float* __restrict__ x, const float* __restrict__ e,
    float* __restrict__ out)
{
    const int row = blockIdx.x;
    const int tid = threadIdx.x;

    // independent prologue (overlaps primary grid tail)
    const float4 xv = ((const float4*)(x + (size_t)row * TLEN))[tid];
    const float ev = e[0];

    asm volatile("griddepcontrol.wait;" ::: "memory");

    // issue K and z0 loads together, right after the gate
    const float4 kv = __ldcg(&((const float4*)g_K)[tid]);
    const float z0 = __ldcg(&g_z0);

    float s = xv.x * kv.x + xv.y * kv.y + xv.z * kv.z + xv.w * kv.w;
    #pragma unroll
    for (int off = 16; off; off >>= 1) s += __shfl_down_sync(0xffffffffu, s, off);

    __shared__ float sp[32];
    const int warp = tid >> 5, lane = tid & 31;
    if (lane == 0) sp[warp] = s;
    __syncthreads();

    if (warp == 0) {
        float t = sp[lane];
        #pragma unroll
        for (int off = 16; off; off >>= 1) t += __shfl_down_sync(0xffffffffu, t, off);
        if (lane == 0) out[row] = t + z0 + ev;
    }
}

extern "C" void kernel_launch(void* const* d_in, const int* in_sizes, int n_in,
                              void* d_out, int out_size)
{
    const float* x = (const float*)d_in[0];   // [B, T]
    const float* a = (const float*)d_in[1];   // [H]
    const float* b = (const float*)d_in[2];   // [H]
    const float* c = (const float*)d_in[3];   // [H]
    const float* w = (const float*)d_in[4];   // [H]
    const float* e = (const float*)d_in[5];   // [1]
    float* out = (float*)d_out;               // [B]

    build_K_kernel<<<NCHUNK, HDIM>>>(a, b, c, w);

    // dot as programmatic dependent of build_K (PDL edge; graph-capturable)
    cudaLaunchAttribute attrs[1];
    attrs[0].id = cudaLaunchAttributeProgrammaticStreamSerialization;
    attrs[0].val.programmaticStreamSerializationAllowed = 1;
    cudaLaunchConfig_t cfg = {};
    cfg.gridDim  = dim3(BATCH);
    cfg.blockDim = dim3(1024);
    cfg.dynamicSmemBytes = 0;
    cfg.stream = 0;
    cfg.attrs = attrs;
    cfg.numAttrs = 1;
    cudaLaunchKernelEx(&cfg, dot_kernel, x, e, out);
}